// round 12
// baseline (speedup 1.0000x reference)
#include <cuda_runtime.h>
#include <cuda_fp16.h>
#include <stdint.h>

#define BATCH 100000
#define SEQ   28
#define IND   28
#define HID   64
#define OUTD  10
#define TPB   128
#define ROWS  16
#define NGRID (BATCH/ROWS)    // 6250, exact
#define SEQIN (SEQ*IND)

// ---- smem byte offsets (all 16B aligned) ----
// wx: extended W_ih' [256 rows][32 k] f16, row stride 64B.
//     rows 0-63 r, 64-127 z, 128-191 i_n, 192-255 h_n(zeros); col28 = biases.
// wh: W_hh [192 rows][64 k] f16, row stride 128B.
// hbuf[2]: h as [unit 0..63][row 0..15] f16, unit stride 48B (24 halves, 16 used)
// xbuf[2]: x_t' as [row 0..15][k 0..31] f16, row stride 80B (40 halves); k28=1.0
#define OFF_WX   0
#define OFF_WH   16384
#define OFF_HB0  (OFF_WH + 24576)     // 40960
#define OFF_HB1  (OFF_HB0 + 3072)     // 44032
#define OFF_XB0  (OFF_HB1 + 3072)     // 47104
#define OFF_XB1  (OFF_XB0 + 1280)     // 48384
#define OFF_WO   (OFF_XB1 + 1280)     // 49664
#define OFF_BO   (OFF_WO + 2560)      // 52224
#define SMEM_TOTAL (OFF_BO + 64)      // 52288

// ---------------- helpers ----------------
__device__ __forceinline__ uint32_t smem_u32(const void* p) {
    uint32_t a;
    asm("{ .reg .u64 t; cvta.to.shared.u64 t, %1; cvt.u32.u64 %0, t; }" : "=r"(a) : "l"(p));
    return a;
}
__device__ __forceinline__ uint32_t lds32(uint32_t a) {
    uint32_t v; asm volatile("ld.shared.b32 %0, [%1];" : "=r"(v) : "r"(a)); return v;
}
__device__ __forceinline__ void sts32(uint32_t a, uint32_t v) {
    asm volatile("st.shared.b32 [%0], %1;" :: "r"(a), "r"(v) : "memory");
}
__device__ __forceinline__ void ldsm_x4(uint32_t addr, uint32_t& r0, uint32_t& r1,
                                        uint32_t& r2, uint32_t& r3) {
    asm volatile("ldmatrix.sync.aligned.m8n8.x4.shared.b16 {%0,%1,%2,%3}, [%4];"
                 : "=r"(r0), "=r"(r1), "=r"(r2), "=r"(r3) : "r"(addr));
}
__device__ __forceinline__ void ldsm_x4t(uint32_t addr, uint32_t& r0, uint32_t& r1,
                                         uint32_t& r2, uint32_t& r3) {
    asm volatile("ldmatrix.sync.aligned.m8n8.x4.trans.shared.b16 {%0,%1,%2,%3}, [%4];"
                 : "=r"(r0), "=r"(r1), "=r"(r2), "=r"(r3) : "r"(addr));
}
__device__ __forceinline__ void mma_h(uint32_t* c, const uint32_t* a, uint32_t b0, uint32_t b1) {
    asm volatile(
        "mma.sync.aligned.m16n8k16.row.col.f16.f16.f16.f16 "
        "{%0,%1}, {%2,%3,%4,%5}, {%6,%7}, {%0,%1};"
        : "+r"(c[0]), "+r"(c[1])
        : "r"(a[0]), "r"(a[1]), "r"(a[2]), "r"(a[3]), "r"(b0), "r"(b1));
}
__device__ __forceinline__ uint32_t tanh2u(uint32_t x) {
    uint32_t y; asm("tanh.approx.f16x2 %0, %1;" : "=r"(y) : "r"(x)); return y;
}
__device__ __forceinline__ __half2 u2h(uint32_t u) { return *reinterpret_cast<__half2*>(&u); }
__device__ __forceinline__ uint32_t h2u(__half2 h) { return *reinterpret_cast<uint32_t*>(&h); }
__device__ __forceinline__ __half2 sig2(__half2 x) {
    const __half2 half_ = __float2half2_rn(0.5f);
    return __hfma2(half_, u2h(tanh2u(h2u(__hmul2(x, half_)))), half_);
}
__device__ __forceinline__ uint32_t gru2(uint32_t rs, uint32_t zs, uint32_t is,
                                         uint32_t hs, uint32_t ho) {
    __half2 r = sig2(u2h(rs));
    __half2 z = sig2(u2h(zs));
    __half2 n = u2h(tanh2u(h2u(__hfma2(r, u2h(hs), u2h(is)))));
    return h2u(__hfma2(z, __hsub2(u2h(ho), n), n));   // (1-z)*n + z*h
}

__global__ void __launch_bounds__(TPB, 3)
gru_mma_kernel(const float* __restrict__ x,
               const float* __restrict__ Wih,
               const float* __restrict__ Whh,
               const float* __restrict__ bih,
               const float* __restrict__ bhh,
               const float* __restrict__ Wout,
               const float* __restrict__ bout,
               float* __restrict__ out)
{
    extern __shared__ char smraw[];
    const int tid = threadIdx.x;
    const int lane = tid & 31, wid = tid >> 5;
    const int q = lane & 3, g = lane >> 2;

    __half* wx   = (__half*)(smraw + OFF_WX);
    __half* wh   = (__half*)(smraw + OFF_WH);
    __half* hb0p = (__half*)(smraw + OFF_HB0);
    __half* xb0p = (__half*)(smraw + OFF_XB0);
    float*  wo   = (float*)(smraw + OFF_WO);
    float*  bo   = (float*)(smraw + OFF_BO);

    // ---- stage extended W_ih' (biases folded into col 28) ----
    for (int s = tid; s < 256 * 32; s += TPB) {
        int row = s >> 5, k = s & 31;
        int gate = row >> 6, u = row & 63;
        float v = 0.0f;
        if (k < IND) { if (gate < 3) v = Wih[(gate * 64 + u) * IND + k]; }
        else if (k == IND) {
            if      (gate == 0) v = bih[u] + bhh[u];
            else if (gate == 1) v = bih[64 + u] + bhh[64 + u];
            else if (gate == 2) v = bih[128 + u];
            else                v = bhh[128 + u];
        }
        wx[row * 32 + k] = __float2half_rn(v);
    }
    // ---- stage W_hh ----
    for (int s = tid; s < 192 * 64; s += TPB)
        wh[s] = __float2half_rn(Whh[s]);
    // ---- zero h buffer 0 (h_0 = 0), incl. padding ----
    for (int s = tid; s < 64 * 24; s += TPB) hb0p[s] = __float2half_rn(0.0f);
    // ---- stage x(t=0) into xbuf0 ----
    const int rowbase = blockIdx.x * ROWS;
    for (int s = tid; s < ROWS * 32; s += TPB) {
        int row = s >> 5, k = s & 31;
        float v = (k < IND) ? x[(size_t)(rowbase + row) * SEQIN + k]
                            : (k == IND ? 1.0f : 0.0f);
        xb0p[row * 40 + k] = __float2half_rn(v);
    }
    for (int s = tid; s < OUTD * HID; s += TPB) wo[s] = Wout[s];
    if (tid < OUTD) bo[tid] = bout[tid];
    __syncthreads();

    // ---- persistent A fragments (weights as A operand) ----
    const uint32_t smb = smem_u32(smraw);
    const int ub = wid * 16;                 // this warp's unit slice [ub, ub+16)
    uint32_t Axw[4][2][4];                   // x-GEMM A: gates r,z,i_n,h_n(bias-only)
#pragma unroll
    for (int gi = 0; gi < 4; gi++)
#pragma unroll
        for (int kt = 0; kt < 2; kt++) {
            const uint32_t r0a = smb + OFF_WX +
                (uint32_t)((gi * 64 + ub + g) * 64 + (kt * 16 + 2 * q) * 2);
            const uint32_t r1a = r0a + 8 * 64;
            Axw[gi][kt][0] = lds32(r0a);
            Axw[gi][kt][1] = lds32(r1a);
            Axw[gi][kt][2] = lds32(r0a + 16);
            Axw[gi][kt][3] = lds32(r1a + 16);
        }
    uint32_t Ahw[3][4][4];                   // h-GEMM A: gates r,z,h_n
#pragma unroll
    for (int gi = 0; gi < 3; gi++) {
        const int gr = (gi == 2 ? 128 : gi * 64) + ub;
#pragma unroll
        for (int kt = 0; kt < 4; kt++) {
            const uint32_t r0a = smb + OFF_WH +
                (uint32_t)((gr + g) * 128 + (kt * 16 + 2 * q) * 2);
            const uint32_t r1a = r0a + 8 * 128;
            Ahw[gi][kt][0] = lds32(r0a);
            Ahw[gi][kt][1] = lds32(r1a);
            Ahw[gi][kt][2] = lds32(r0a + 16);
            Ahw[gi][kt][3] = lds32(r1a + 16);
        }
    }

    // ---- per-lane ldmatrix / h addresses ----
    const int mat = lane >> 3, rr = lane & 7;
    const int ntm = mat >> 1, khm = mat & 1;
    const uint32_t hoff = (uint32_t)((khm * 8 + rr) * 48 + ntm * 16);
    const uint32_t xoff = (uint32_t)((ntm * 8 + rr) * 80 + khm * 16);
    const uint32_t hbA = smb + OFF_HB0, hbB = smb + OFF_HB1;
    const uint32_t xbA = smb + OFF_XB0, xbB = smb + OFF_XB1;
    uint32_t hooff[2][2];
#pragma unroll
    for (int nt = 0; nt < 2; nt++)
#pragma unroll
        for (int pr = 0; pr < 2; pr++)
            hooff[nt][pr] = (uint32_t)((ub + g + pr * 8) * 48 + (nt * 8 + 2 * q) * 2);

#pragma unroll 1
    for (int t = 0; t < SEQ; t++) {
        const uint32_t hb_c = (t & 1) ? hbB : hbA;
        const uint32_t hb_n = (t & 1) ? hbA : hbB;
        const uint32_t xb_c = (t & 1) ? xbB : xbA;
        __half* xb_np = (__half*)(smraw + ((t & 1) ? OFF_XB0 : OFF_XB1));

        // ---- stage x(t+1) into the other buffer (LDG latency hides under MMAs) ----
        if (t + 1 < SEQ) {
            const float* xs = x + (size_t)rowbase * SEQIN + (size_t)(t + 1) * IND;
#pragma unroll
            for (int i = 0; i < 4; i++) {
                int s = tid + i * TPB;
                int row = s >> 5, k = s & 31;
                float v = (k < IND) ? xs[(size_t)row * SEQIN + k]
                                    : (k == IND ? 1.0f : 0.0f);
                xb_np[row * 40 + k] = __float2half_rn(v);
            }
        }

        uint32_t acc[4][2][2];   // [gate r,z,i_n,h_n][ntile rows 0-8/8-16][unit g / g+8]
#pragma unroll
        for (int gi = 0; gi < 4; gi++)
#pragma unroll
            for (int nt = 0; nt < 2; nt++) { acc[gi][nt][0] = 0u; acc[gi][nt][1] = 0u; }

        // ---- h GEMM: B = h[k=unit][n=row] via ldmatrix.trans ----
#pragma unroll
        for (int kt = 0; kt < 4; kt++) {
            uint32_t b0, b1, b2, b3;
            ldsm_x4t(hb_c + (uint32_t)(kt * 768) + hoff, b0, b1, b2, b3);
            mma_h(acc[0][0], Ahw[0][kt], b0, b1);
            mma_h(acc[0][1], Ahw[0][kt], b2, b3);
            mma_h(acc[1][0], Ahw[1][kt], b0, b1);
            mma_h(acc[1][1], Ahw[1][kt], b2, b3);
            mma_h(acc[3][0], Ahw[2][kt], b0, b1);
            mma_h(acc[3][1], Ahw[2][kt], b2, b3);
        }
        // ---- x GEMM (+ all biases via k=28 col, x row28 = 1.0) ----
#pragma unroll
        for (int kt = 0; kt < 2; kt++) {
            uint32_t b0, b1, b2, b3;
            ldsm_x4(xb_c + (uint32_t)(kt * 32) + xoff, b0, b1, b2, b3);
#pragma unroll
            for (int gi = 0; gi < 4; gi++) {
                mma_h(acc[gi][0], Axw[gi][kt], b0, b1);
                mma_h(acc[gi][1], Axw[gi][kt], b2, b3);
            }
        }
        // ---- epilogue: 4 gru2 per lane; h_new -> other h buffer ----
#pragma unroll
        for (int nt = 0; nt < 2; nt++)
#pragma unroll
            for (int pr = 0; pr < 2; pr++) {
                uint32_t ho = lds32(hb_c + hooff[nt][pr]);
                uint32_t hn = gru2(acc[0][nt][pr], acc[1][nt][pr],
                                   acc[2][nt][pr], acc[3][nt][pr], ho);
                sts32(hb_n + hooff[nt][pr], hn);
            }
        __syncthreads();
    }

    // ---- output projection (final h is in buffer 0: SEQ is even) ----
    for (int s = tid; s < ROWS * OUTD; s += TPB) {
        int row = s / OUTD, o = s % OUTD;
        float sum = bo[o];
#pragma unroll
        for (int u = 0; u < HID; u++)
            sum += __half2float(hb0p[u * 24 + row]) * wo[o * HID + u];
        out[(size_t)(rowbase + row) * OUTD + o] = sum;
    }
}

extern "C" void kernel_launch(void* const* d_in, const int* in_sizes, int n_in,
                              void* d_out, int out_size)
{
    const float* x    = (const float*)d_in[0];
    const float* Wih  = (const float*)d_in[1];
    const float* Whh  = (const float*)d_in[2];
    const float* bih  = (const float*)d_in[3];
    const float* bhh  = (const float*)d_in[4];
    const float* Wout = (const float*)d_in[5];
    const float* bout = (const float*)d_in[6];
    float* out = (float*)d_out;

    cudaFuncSetAttribute(gru_mma_kernel,
                         cudaFuncAttributeMaxDynamicSharedMemorySize, SMEM_TOTAL);

    gru_mma_kernel<<<NGRID, TPB, SMEM_TOTAL>>>(x, Wih, Whh, bih, bhh, Wout, bout, out);
}

// round 13
// speedup vs baseline: 1.6316x; 1.6316x over previous
#include <cuda_runtime.h>
#include <cuda_fp16.h>
#include <stdint.h>

#define BATCH 100000
#define SEQ   28
#define IND   28
#define HID   64
#define OUTD  10
#define TPB   128
#define TILES 2
#define CTAROWS 32
#define NGRID (BATCH/CTAROWS)   // 3125 exact
#define SEQIN (SEQ*IND)

// ---- smem byte offsets ----
// wx: extended W_ih' [256 rows][32 k] f16, row stride 64B (col 28 = biases)
// wh: W_hh [192][64] f16, stride 128B
// hb: 4 bufs (tile*2+phase) of [64 units][16 rows] f16, unit stride 48B -> 3072 B
// xb: 4 bufs (tile*2+phase) of [16 rows][32 k] f16, row stride 80B -> 1280 B
#define OFF_WX 0
#define OFF_WH 16384
#define OFF_HB 40960
#define OFF_XB 53248
#define OFF_WO 58368
#define OFF_BO 60928
#define SMEM_TOTAL 60992

// ---------------- helpers ----------------
__device__ __forceinline__ uint32_t smem_u32(const void* p) {
    uint32_t a;
    asm("{ .reg .u64 t; cvta.to.shared.u64 t, %1; cvt.u32.u64 %0, t; }" : "=r"(a) : "l"(p));
    return a;
}
__device__ __forceinline__ uint32_t pack_f16(float e0, float e1) {
    uint32_t r;
    asm("cvt.rn.f16x2.f32 %0, %1, %2;" : "=r"(r) : "f"(e1), "f"(e0));
    return r;
}
__device__ __forceinline__ uint32_t lds32(uint32_t a) {
    uint32_t v; asm volatile("ld.shared.b32 %0, [%1];" : "=r"(v) : "r"(a)); return v;
}
__device__ __forceinline__ void sts32(uint32_t a, uint32_t v) {
    asm volatile("st.shared.b32 [%0], %1;" :: "r"(a), "r"(v) : "memory");
}
__device__ __forceinline__ void ldsm_x4(uint32_t addr, uint32_t& r0, uint32_t& r1,
                                        uint32_t& r2, uint32_t& r3) {
    asm volatile("ldmatrix.sync.aligned.m8n8.x4.shared.b16 {%0,%1,%2,%3}, [%4];"
                 : "=r"(r0), "=r"(r1), "=r"(r2), "=r"(r3) : "r"(addr));
}
__device__ __forceinline__ void ldsm_x4t(uint32_t addr, uint32_t& r0, uint32_t& r1,
                                         uint32_t& r2, uint32_t& r3) {
    asm volatile("ldmatrix.sync.aligned.m8n8.x4.trans.shared.b16 {%0,%1,%2,%3}, [%4];"
                 : "=r"(r0), "=r"(r1), "=r"(r2), "=r"(r3) : "r"(addr));
}
__device__ __forceinline__ void mma_h(uint32_t* c, const uint32_t* a, uint32_t b0, uint32_t b1) {
    asm volatile(
        "mma.sync.aligned.m16n8k16.row.col.f16.f16.f16.f16 "
        "{%0,%1}, {%2,%3,%4,%5}, {%6,%7}, {%0,%1};"
        : "+r"(c[0]), "+r"(c[1])
        : "r"(a[0]), "r"(a[1]), "r"(a[2]), "r"(a[3]), "r"(b0), "r"(b1));
}
__device__ __forceinline__ uint32_t tanh2u(uint32_t x) {
    uint32_t y; asm("tanh.approx.f16x2 %0, %1;" : "=r"(y) : "r"(x)); return y;
}
__device__ __forceinline__ __half2 u2h(uint32_t u) { return *reinterpret_cast<__half2*>(&u); }
__device__ __forceinline__ uint32_t h2u(__half2 h) { return *reinterpret_cast<uint32_t*>(&h); }
__device__ __forceinline__ __half2 sig2(__half2 x) {
    const __half2 half_ = __float2half2_rn(0.5f);
    return __hfma2(half_, u2h(tanh2u(h2u(__hmul2(x, half_)))), half_);
}
__device__ __forceinline__ uint32_t gru2(uint32_t rs, uint32_t zs, uint32_t is,
                                         uint32_t hs, uint32_t ho) {
    __half2 r = sig2(u2h(rs));
    __half2 z = sig2(u2h(zs));
    __half2 n = u2h(tanh2u(h2u(__hfma2(r, u2h(hs), u2h(is)))));
    return h2u(__hfma2(z, __hsub2(u2h(ho), n), n));   // (1-z)*n + z*h
}

__global__ void __launch_bounds__(TPB, 3)
gru_mma_kernel(const float* __restrict__ x,
               const float* __restrict__ Wih,
               const float* __restrict__ Whh,
               const float* __restrict__ bih,
               const float* __restrict__ bhh,
               const float* __restrict__ Wout,
               const float* __restrict__ bout,
               float* __restrict__ out)
{
    extern __shared__ char smraw[];
    const int tid = threadIdx.x;
    const int lane = tid & 31, wid = tid >> 5;
    const int q = lane & 3, g = lane >> 2;
    const uint32_t smb = smem_u32(smraw);

    __half* wx = (__half*)(smraw + OFF_WX);
    __half* wh = (__half*)(smraw + OFF_WH);
    float*  wo = (float*)(smraw + OFF_WO);
    float*  bo = (float*)(smraw + OFF_BO);

    // ---- stage extended W_ih' (biases folded into col 28) ----
    for (int s = tid; s < 256 * 32; s += TPB) {
        int row = s >> 5, k = s & 31;
        int gate = row >> 6, u = row & 63;
        float v = 0.0f;
        if (k < IND) { if (gate < 3) v = Wih[(gate * 64 + u) * IND + k]; }
        else if (k == IND) {
            if      (gate == 0) v = bih[u] + bhh[u];
            else if (gate == 1) v = bih[64 + u] + bhh[64 + u];
            else if (gate == 2) v = bih[128 + u];
            else                v = bhh[128 + u];
        }
        wx[row * 32 + k] = __float2half_rn(v);
    }
    for (int s = tid; s < 192 * 64; s += TPB) wh[s] = __float2half_rn(Whh[s]);
    // ---- zero phase-0 h buffers of both tiles (incl. padding) ----
    for (int s = tid; s < 1536; s += TPB) {
        ((__half*)(smraw + OFF_HB))[s]        = __float2half_rn(0.0f);
        ((__half*)(smraw + OFF_HB + 6144))[s] = __float2half_rn(0.0f);
    }
    // ---- stage x(t=0), both tiles, phase 0 ----
    const int rowbase = blockIdx.x * CTAROWS;
    for (int s = tid; s < TILES * 16 * 16; s += TPB) {
        int tile = s >> 8, rem = s & 255;
        int row = rem >> 4, kp = rem & 15;
        float2 v;
        if (kp < 14)       v = *(const float2*)(x + (size_t)(rowbase + tile * 16 + row) * SEQIN + 2 * kp);
        else if (kp == 14) v = make_float2(1.0f, 0.0f);
        else               v = make_float2(0.0f, 0.0f);
        sts32(smb + OFF_XB + (uint32_t)(tile * 2 * 1280 + row * 80 + kp * 4),
              pack_f16(v.x, v.y));
    }
    for (int s = tid; s < OUTD * HID; s += TPB) wo[s] = Wout[s];
    if (tid < OUTD) bo[tid] = bout[tid];
    __syncthreads();

    // ---- persistent weight A-fragments (R12-proven layout) ----
    const int ub = wid * 16;
    uint32_t Axw[4][2][4];
#pragma unroll
    for (int gi = 0; gi < 4; gi++)
#pragma unroll
        for (int kt = 0; kt < 2; kt++) {
            const uint32_t r0a = smb + OFF_WX +
                (uint32_t)((gi * 64 + ub + g) * 64 + (kt * 16 + 2 * q) * 2);
            const uint32_t r1a = r0a + 8 * 64;
            Axw[gi][kt][0] = lds32(r0a);
            Axw[gi][kt][1] = lds32(r1a);
            Axw[gi][kt][2] = lds32(r0a + 16);
            Axw[gi][kt][3] = lds32(r1a + 16);
        }
    uint32_t Ahw[3][4][4];
#pragma unroll
    for (int gi = 0; gi < 3; gi++) {
        const int gr = (gi == 2 ? 128 : gi * 64) + ub;
#pragma unroll
        for (int kt = 0; kt < 4; kt++) {
            const uint32_t r0a = smb + OFF_WH +
                (uint32_t)((gr + g) * 128 + (kt * 16 + 2 * q) * 2);
            const uint32_t r1a = r0a + 8 * 128;
            Ahw[gi][kt][0] = lds32(r0a);
            Ahw[gi][kt][1] = lds32(r1a);
            Ahw[gi][kt][2] = lds32(r0a + 16);
            Ahw[gi][kt][3] = lds32(r1a + 16);
        }
    }

    // ---- per-lane ldmatrix / store offsets (R12-proven) ----
    const int mat = lane >> 3, rr = lane & 7;
    const int ntm = mat >> 1, khm = mat & 1;
    const uint32_t hoff = (uint32_t)((khm * 8 + rr) * 48 + ntm * 16);
    const uint32_t xoff = (uint32_t)((ntm * 8 + rr) * 80 + khm * 16);
    uint32_t hooff[2][2];
#pragma unroll
    for (int nt = 0; nt < 2; nt++)
#pragma unroll
        for (int pr = 0; pr < 2; pr++)
            hooff[nt][pr] = (uint32_t)((ub + g + pr * 8) * 48 + (nt * 8 + 2 * q) * 2);

    // ---- x prefetch lane mapping ----
    const int prow = tid >> 3;            // 0..15
    const int pkp  = (tid & 7) * 2;       // kpair base
    const float* xrp0 = x + (size_t)(rowbase + prow) * SEQIN;
    const float* xrp1 = x + (size_t)(rowbase + 16 + prow) * SEQIN;

    uint32_t hown[TILES][4];              // own-unit h (C-frag layout), [nt*2+pr]
#pragma unroll
    for (int tl = 0; tl < TILES; tl++)
#pragma unroll
        for (int i = 0; i < 4; i++) hown[tl][i] = 0u;

#pragma unroll 1
    for (int t = 0; t < SEQ; t++) {
        const int c = t & 1, nph = c ^ 1;

        // ---- prefetch x(t+1) into registers (overlaps MMAs) ----
        uint32_t xpre[TILES][2];
        if (t + 1 < SEQ) {
#pragma unroll
            for (int j = 0; j < 2; j++) {
                const int kp = pkp + j;
                float2 v0, v1;
                if (kp < 14) {
                    v0 = *(const float2*)(xrp0 + (t + 1) * IND + 2 * kp);
                    v1 = *(const float2*)(xrp1 + (t + 1) * IND + 2 * kp);
                } else if (kp == 14) { v0 = make_float2(1.0f, 0.0f); v1 = v0; }
                else                 { v0 = make_float2(0.0f, 0.0f); v1 = v0; }
                xpre[0][j] = pack_f16(v0.x, v0.y);
                xpre[1][j] = pack_f16(v1.x, v1.y);
            }
        }

        uint32_t acc[TILES][4][2][2];
#pragma unroll
        for (int tl = 0; tl < TILES; tl++)
#pragma unroll
            for (int gi = 0; gi < 4; gi++)
#pragma unroll
                for (int nt = 0; nt < 2; nt++) { acc[tl][gi][nt][0] = 0u; acc[tl][gi][nt][1] = 0u; }

        // ---- h GEMM, tiles interleaved ----
#pragma unroll
        for (int kt = 0; kt < 4; kt++)
#pragma unroll
            for (int tl = 0; tl < TILES; tl++) {
                const uint32_t hb_c = smb + OFF_HB + (uint32_t)((tl * 2 + c) * 3072);
                uint32_t b0, b1, b2, b3;
                ldsm_x4t(hb_c + (uint32_t)(kt * 768) + hoff, b0, b1, b2, b3);
                mma_h(acc[tl][0][0], Ahw[0][kt], b0, b1);
                mma_h(acc[tl][0][1], Ahw[0][kt], b2, b3);
                mma_h(acc[tl][1][0], Ahw[1][kt], b0, b1);
                mma_h(acc[tl][1][1], Ahw[1][kt], b2, b3);
                mma_h(acc[tl][3][0], Ahw[2][kt], b0, b1);
                mma_h(acc[tl][3][1], Ahw[2][kt], b2, b3);
            }
        // ---- x GEMM (+ biases via k=28 col) ----
#pragma unroll
        for (int kt = 0; kt < 2; kt++)
#pragma unroll
            for (int tl = 0; tl < TILES; tl++) {
                const uint32_t xb_c = smb + OFF_XB + (uint32_t)((tl * 2 + c) * 1280);
                uint32_t b0, b1, b2, b3;
                ldsm_x4(xb_c + (uint32_t)(kt * 32) + xoff, b0, b1, b2, b3);
#pragma unroll
                for (int gi = 0; gi < 4; gi++) {
                    mma_h(acc[tl][gi][0], Axw[gi][kt], b0, b1);
                    mma_h(acc[tl][gi][1], Axw[gi][kt], b2, b3);
                }
            }

        // ---- epilogue: gates on own units; h_old from regs; h_new -> smem + regs ----
#pragma unroll
        for (int tl = 0; tl < TILES; tl++) {
            const uint32_t hb_n = smb + OFF_HB + (uint32_t)((tl * 2 + nph) * 3072);
#pragma unroll
            for (int nt = 0; nt < 2; nt++)
#pragma unroll
                for (int pr = 0; pr < 2; pr++) {
                    uint32_t hn = gru2(acc[tl][0][nt][pr], acc[tl][1][nt][pr],
                                       acc[tl][2][nt][pr], acc[tl][3][nt][pr],
                                       hown[tl][nt * 2 + pr]);
                    hown[tl][nt * 2 + pr] = hn;
                    sts32(hb_n + hooff[nt][pr], hn);
                }
        }

        // ---- commit prefetched x(t+1) ----
        if (t + 1 < SEQ) {
#pragma unroll
            for (int tl = 0; tl < TILES; tl++)
#pragma unroll
                for (int j = 0; j < 2; j++)
                    sts32(smb + OFF_XB + (uint32_t)((tl * 2 + nph) * 1280 + prow * 80 + (pkp + j) * 4),
                          xpre[tl][j]);
        }
        __syncthreads();
    }

    // ---- output projection (final h in phase 0 of each tile: SEQ even) ----
    for (int s = tid; s < CTAROWS * OUTD; s += TPB) {
        int row = s / OUTD, o = s % OUTD;
        int tile = row >> 4, r16 = row & 15;
        const __half* hp = (const __half*)(smraw + OFF_HB + tile * 2 * 3072);
        float sum = bo[o];
#pragma unroll
        for (int u = 0; u < HID; u++)
            sum += __half2float(hp[u * 24 + r16]) * wo[o * HID + u];
        out[(size_t)(rowbase + row) * OUTD + o] = sum;
    }
}

extern "C" void kernel_launch(void* const* d_in, const int* in_sizes, int n_in,
                              void* d_out, int out_size)
{
    const float* x    = (const float*)d_in[0];
    const float* Wih  = (const float*)d_in[1];
    const float* Whh  = (const float*)d_in[2];
    const float* bih  = (const float*)d_in[3];
    const float* bhh  = (const float*)d_in[4];
    const float* Wout = (const float*)d_in[5];
    const float* bout = (const float*)d_in[6];
    float* out = (float*)d_out;

    cudaFuncSetAttribute(gru_mma_kernel,
                         cudaFuncAttributeMaxDynamicSharedMemorySize, SMEM_TOTAL);

    gru_mma_kernel<<<NGRID, TPB, SMEM_TOTAL>>>(x, Wih, Whh, bih, bhh, Wout, bout, out);
}

// round 14
// speedup vs baseline: 2.5430x; 1.5586x over previous
#include <cuda_runtime.h>
#include <cuda_fp16.h>
#include <stdint.h>

#define BATCH 100000
#define SEQ   28
#define IND   28
#define HID   64
#define OUTD  10
#define TPB   128
#define WARPS (TPB/32)
#define MTILE (WARPS*16)                    // 64 batch rows per CTA
#define NGRID ((BATCH + MTILE - 1)/MTILE)   // 1563

// ---------------- shared memory ----------------
// B fragments as ldmatrix-ready 8x8 f16 matrices (layout identical to R9).
// bxm now holds the EXTENDED W_ih': col 28 = bias(r/z/i_n), cols 29-31 = 0.
struct SmemLayout {
    __half bxm[2 * 12 * 256];     // W_ih' frags: 12288 B
    __half bhm[4 * 12 * 256];     // W_hh frags: 24576 B
    uint32_t bias_frag[32 * 4];   // f16x2 bias per (nt, q); only nt 24-31 used in loop
    float wout[OUTD][HID];
    float bout[OUTD];
};
#define OFF_BXM 0
#define OFF_BHM (2 * 12 * 512)
#define OFF_BF  (OFF_BHM + 4 * 12 * 512)

// ---------------- helpers ----------------
__device__ __forceinline__ uint32_t smem_u32(const void* p) {
    uint32_t a;
    asm("{ .reg .u64 t; cvta.to.shared.u64 t, %1; cvt.u32.u64 %0, t; }" : "=r"(a) : "l"(p));
    return a;
}
__device__ __forceinline__ uint32_t pack_f16(float e0, float e1) {
    uint32_t r;
    asm("cvt.rn.f16x2.f32 %0, %1, %2;" : "=r"(r) : "f"(e1), "f"(e0));
    return r;
}
__device__ __forceinline__ float2 unpack_f16(uint32_t p) {
    __half2 h = *reinterpret_cast<__half2*>(&p);
    return __half22float2(h);
}
__device__ __forceinline__ void ldsm_x4(uint32_t addr, uint32_t& r0, uint32_t& r1,
                                        uint32_t& r2, uint32_t& r3) {
    asm volatile("ldmatrix.sync.aligned.m8n8.x4.shared.b16 {%0,%1,%2,%3}, [%4];"
                 : "=r"(r0), "=r"(r1), "=r"(r2), "=r"(r3) : "r"(addr));
}
__device__ __forceinline__ void mma_h(uint32_t* c, const uint32_t* a, uint32_t b0, uint32_t b1) {
    asm volatile(
        "mma.sync.aligned.m16n8k16.row.col.f16.f16.f16.f16 "
        "{%0,%1}, {%2,%3,%4,%5}, {%6,%7}, {%0,%1};"
        : "+r"(c[0]), "+r"(c[1])
        : "r"(a[0]), "r"(a[1]), "r"(a[2]), "r"(a[3]), "r"(b0), "r"(b1));
}
__device__ __forceinline__ uint32_t tanh2u(uint32_t x) {
    uint32_t y;
    asm("tanh.approx.f16x2 %0, %1;" : "=r"(y) : "r"(x));
    return y;
}
__device__ __forceinline__ __half2 u2h(uint32_t u) { return *reinterpret_cast<__half2*>(&u); }
__device__ __forceinline__ uint32_t h2u(__half2 h) { return *reinterpret_cast<uint32_t*>(&h); }
__device__ __forceinline__ __half2 sig2(__half2 x) {
    const __half2 half_ = __float2half2_rn(0.5f);
    return __hfma2(half_, u2h(tanh2u(h2u(__hmul2(x, half_)))), half_);
}
__device__ __forceinline__ uint32_t gru2(uint32_t rs, uint32_t zs, uint32_t is,
                                         uint32_t hs, uint32_t ho) {
    __half2 r = sig2(u2h(rs));
    __half2 z = sig2(u2h(zs));
    __half2 n = u2h(tanh2u(h2u(__hfma2(r, u2h(hs), u2h(is)))));
    return h2u(__hfma2(z, __hsub2(u2h(ho), n), n));   // (1-z)*n + z*h
}

__global__ void __launch_bounds__(TPB, 4)
gru_mma_kernel(const float* __restrict__ x,
               const float* __restrict__ Wih,
               const float* __restrict__ Whh,
               const float* __restrict__ bih,
               const float* __restrict__ bhh,
               const float* __restrict__ Wout,
               const float* __restrict__ bout,
               float* __restrict__ out)
{
    extern __shared__ char smraw[];
    SmemLayout* sm = (SmemLayout*)smraw;
    const int tid = threadIdx.x;

    // ---- stage extended W_ih' fragments (bias in col 28 for r/z/i_n) ----
    for (int s = tid; s < 2 * 12 * 256; s += TPB) {
        int kk = s & 7, g = (s >> 3) & 7, mat = (s >> 6) & 3;
        int blk = s >> 8;
        int pair = blk % 12, kt = blk / 12;
        int n = pair * 16 + (mat >> 1) * 8 + g;        // 0..191 (r,z,i_n rows)
        int k = kt * 16 + (mat & 1) * 8 + kk;          // 0..31
        float v = 0.0f;
        if (k < IND)       v = Wih[n * IND + k];
        else if (k == IND) v = (n < 128) ? (bih[n] + bhh[n]) : bih[n];
        sm->bxm[s] = __float2half_rn(v);
    }
    // ---- stage W_hh fragments (ntl<16 -> r,z rows; else h_n rows) ----
    for (int s = tid; s < 4 * 12 * 256; s += TPB) {
        int kk = s & 7, g = (s >> 3) & 7, mat = (s >> 6) & 3;
        int blk = s >> 8;
        int pair = blk % 12, kt = blk / 12;
        int ntl = pair * 2 + (mat >> 1);
        int ngl = (ntl < 16 ? ntl : ntl + 8) * 8 + g;
        int row = (ngl < 128) ? ngl : ngl - 64;
        int k = kt * 16 + (mat & 1) * 8 + kk;
        sm->bhm[s] = __float2half_rn(Whh[row * HID + k]);
    }
    // ---- bias table (only h_n entries, nt 24-31, are read in the loop) ----
    for (int s = tid; s < 32 * 4; s += TPB) {
        int nt = s >> 2, qq = s & 3;
        int j = (nt & 7) * 8 + 2 * qq;
        float b0 = 0.0f, b1 = 0.0f;
        if (nt >= 24) { b0 = bhh[128 + j]; b1 = bhh[128 + j + 1]; }
        sm->bias_frag[s] = pack_f16(b0, b1);
    }
    for (int i = tid; i < OUTD * HID; i += TPB) ((float*)sm->wout)[i] = Wout[i];
    for (int i = tid; i < OUTD; i += TPB) sm->bout[i] = bout[i];
    __syncthreads();

    const int lane = tid & 31;
    const int wid = tid >> 5;
    const int q = lane & 3, g = lane >> 2;
    const int row0 = blockIdx.x * MTILE + wid * 16 + g;
    const int row1 = row0 + 8;
    const bool v0 = row0 < BATCH, v1 = row1 < BATCH;

    const uint32_t smb = smem_u32(smraw);
    const uint32_t bx_base = smb + OFF_BXM + (uint32_t)lane * 16u;
    const uint32_t bh_base = smb + OFF_BHM + (uint32_t)lane * 16u;
    const uint32_t bf_base = smb + OFF_BF + (uint32_t)q * 4u;

    uint32_t acc[32][2];        // f16x2 accumulators (raw regs)
    uint32_t Ax[2][4], Ah[4][4];
#pragma unroll
    for (int kt = 0; kt < 4; kt++)
#pragma unroll
        for (int r = 0; r < 4; r++) Ah[kt][r] = 0u;

    const float* xr0 = x + (size_t)(v0 ? row0 : 0) * (SEQ * IND);
    const float* xr1 = x + (size_t)(v1 ? row1 : 0) * (SEQ * IND);

#pragma unroll 2
    for (int t = 0; t < SEQ; t++) {
        // ---- load x_t, convert to f16 A-fragments; pad col 28 = 1.0 (bias lane) ----
#pragma unroll
        for (int kt = 0; kt < 2; kt++)
#pragma unroll
            for (int half = 0; half < 2; half++) {
                const int kb = kt * 16 + 2 * q + half * 8;
                float2 p0, p1;
                if (kb < IND) {
                    p0 = v0 ? *(const float2*)(xr0 + t * IND + kb) : make_float2(0.0f, 0.0f);
                    p1 = v1 ? *(const float2*)(xr1 + t * IND + kb) : make_float2(0.0f, 0.0f);
                } else if (kb == IND) {
                    p0 = make_float2(1.0f, 0.0f);   // bias multiplier
                    p1 = make_float2(1.0f, 0.0f);
                } else {
                    p0 = make_float2(0.0f, 0.0f);
                    p1 = make_float2(0.0f, 0.0f);
                }
                Ax[kt][half * 2 + 0] = pack_f16(p0.x, p0.y);
                Ax[kt][half * 2 + 1] = pack_f16(p1.x, p1.y);
            }

        // ---- init accumulators: r/z/i_n zero (bias comes via x-GEMM); h_n from table ----
#pragma unroll
        for (int nt = 0; nt < 24; nt++) { acc[nt][0] = 0u; acc[nt][1] = 0u; }
#pragma unroll
        for (int l = 0; l < 8; l++) {
            uint32_t bf;
            asm volatile("ld.shared.b32 %0, [%1];" : "=r"(bf)
                         : "r"(bf_base + (uint32_t)(24 + l) * 16u));
            acc[24 + l][0] = bf; acc[24 + l][1] = bf;
        }

        // ---- h GEMM: D[:,{0:128,192:256}] += h @ W_hh^T ----
#pragma unroll
        for (int kt = 0; kt < 4; kt++) {
#pragma unroll
            for (int p = 0; p < 12; p++) {
                uint32_t b0, b1, b2, b3;
                ldsm_x4(bh_base + (uint32_t)(kt * 12 + p) * 512u, b0, b1, b2, b3);
                const int ntl_e = 2 * p, ntl_o = 2 * p + 1;
                const int nt_e = (ntl_e < 16) ? ntl_e : ntl_e + 8;
                const int nt_o = (ntl_o < 16) ? ntl_o : ntl_o + 8;
                mma_h(acc[nt_e], Ah[kt], b0, b1);
                mma_h(acc[nt_o], Ah[kt], b2, b3);
            }
        }

        // ---- x GEMM: D[:,0:192] += x' @ W_ih'^T (includes biases via k=28) ----
#pragma unroll
        for (int kt = 0; kt < 2; kt++) {
#pragma unroll
            for (int p = 0; p < 12; p++) {
                uint32_t b0, b1, b2, b3;
                ldsm_x4(bx_base + (uint32_t)(kt * 12 + p) * 512u, b0, b1, b2, b3);
                mma_h(acc[2 * p],     Ax[kt], b0, b1);
                mma_h(acc[2 * p + 1], Ax[kt], b2, b3);
            }
        }

        // ---- epilogue: all-f16x2 gates directly on acc regs; h_new -> Ah ----
#pragma unroll
        for (int i = 0; i < 8; i++) {
            const int kt = i >> 1;
            const int ra = (i & 1) * 2;
            Ah[kt][ra]     = gru2(acc[i][0], acc[8 + i][0], acc[16 + i][0],
                                  acc[24 + i][0], Ah[kt][ra]);
            Ah[kt][ra + 1] = gru2(acc[i][1], acc[8 + i][1], acc[16 + i][1],
                                  acc[24 + i][1], Ah[kt][ra + 1]);
        }
    }

    // ---- output projection: out = hT @ W_out^T + b_out ----
    float hf[8][4];
#pragma unroll
    for (int i = 0; i < 8; i++) {
        const int kt = i >> 1, ra = (i & 1) * 2;
        float2 a = unpack_f16(Ah[kt][ra]);
        float2 b = unpack_f16(Ah[kt][ra + 1]);
        hf[i][0] = a.x; hf[i][1] = a.y; hf[i][2] = b.x; hf[i][3] = b.y;
    }
#pragma unroll
    for (int o = 0; o < OUTD; o++) {
        float s0 = 0.0f, s1 = 0.0f;
#pragma unroll
        for (int i = 0; i < 8; i++) {
            int j0 = i * 8 + 2 * q;
            float2 w = *(const float2*)&sm->wout[o][j0];
            s0 += hf[i][0] * w.x + hf[i][1] * w.y;
            s1 += hf[i][2] * w.x + hf[i][3] * w.y;
        }
        s0 += __shfl_xor_sync(0xffffffffu, s0, 1);
        s0 += __shfl_xor_sync(0xffffffffu, s0, 2);
        s1 += __shfl_xor_sync(0xffffffffu, s1, 1);
        s1 += __shfl_xor_sync(0xffffffffu, s1, 2);
        if (q == 0) {
            float bo = sm->bout[o];
            if (v0) out[(size_t)row0 * OUTD + o] = s0 + bo;
            if (v1) out[(size_t)row1 * OUTD + o] = s1 + bo;
        }
    }
}

extern "C" void kernel_launch(void* const* d_in, const int* in_sizes, int n_in,
                              void* d_out, int out_size)
{
    const float* x    = (const float*)d_in[0];
    const float* Wih  = (const float*)d_in[1];
    const float* Whh  = (const float*)d_in[2];
    const float* bih  = (const float*)d_in[3];
    const float* bhh  = (const float*)d_in[4];
    const float* Wout = (const float*)d_in[5];
    const float* bout = (const float*)d_in[6];
    float* out = (float*)d_out;

    const int smem_bytes = (int)sizeof(SmemLayout);
    cudaFuncSetAttribute(gru_mma_kernel,
                         cudaFuncAttributeMaxDynamicSharedMemorySize, smem_bytes);

    gru_mma_kernel<<<NGRID, TPB, smem_bytes>>>(x, Wih, Whh, bih, bhh, Wout, bout, out);
}